// round 17
// baseline (speedup 1.0000x reference)
#include <cuda_runtime.h>

// FINAL (converged; certified R8/R10–R16, best sample 96.77us) —
// Controlled-SX on qutrits (dim=3, 16 qudits), ctrl=2, obj=5.
//   d2!=1          : out[i] = in[i]
//   d2==1, d5==0   : out[i] = in[i + 3^10]
//   d2==1, d5==1   : out[i] = in[i - 3^10]
//   d2==1, d5==2   : out[i] = 0
// Evidence across 16 rounds (all optimization classes measured):
//  - 1 thread = 1 float4 quad (lane stride 16B) is the coalescing optimum;
//    wider per-thread footprints (2xLDG.128 or LDG.256) crack into
//    half-sector accesses and halve L1 throughput (R4, R9: ~2x slower).
//  - Extra MLP (R5), streaming hints (R7), grid-stride (R6): flat or worse.
//  - At the HBM3e mixed r/w stream ceiling: ~6.3 TB/s ncu DRAM (~79% spec),
//    ~6.9 TB/s application-effective (zero region never read).
//  - CE/TMA offload rejected: B300 LTS cap is path-independent.
//  - Residuals irreducible: gather sector overhead ~0.5%, out_im phase
//    permanently 4B-odd (n odd), zero-region writes mandatory.
// out_im = d_out + n with n odd -> 4B-aligned only: scalar stores for im.

static constexpr int S5 = 59049;    // 3^10
static constexpr int S2 = 1594323;  // 3^13 = 27 * S5

__device__ __forceinline__ void scalar_one(const float* __restrict__ in_re,
                                           const float* __restrict__ in_im,
                                           float* __restrict__ out_re,
                                           float* __restrict__ out_im,
                                           int idx)
{
    int q5 = idx / S5;
    int d5 = q5 % 3;
    int d2 = (q5 / 27) % 3;
    float vr, vi;
    if (d2 != 1) {
        vr = __ldcs(in_re + idx);
        vi = __ldcs(in_im + idx);
    } else if (d5 == 0) {
        vr = __ldcs(in_re + idx + S5);
        vi = __ldcs(in_im + idx + S5);
    } else if (d5 == 1) {
        vr = __ldcs(in_re + idx - S5);
        vi = __ldcs(in_im + idx - S5);
    } else {
        vr = 0.0f; vi = 0.0f;
    }
    __stcs(out_re + idx, vr);
    __stcs(out_im + idx, vi);
}

__global__ void __launch_bounds__(512)
sx_apply_final(const float* __restrict__ in_re,
               const float* __restrict__ in_im,
               float* __restrict__ out_re,
               float* __restrict__ out_im,   // 4B-aligned only: scalar stores
               int n, int nq)
{
    int q = blockIdx.x * blockDim.x + threadIdx.x;
    if (q >= nq) return;
    int i = q << 2;

    int q5 = i / S5;                 // magic-mul divide
    int r5 = i - q5 * S5;
    int d5 = q5 % 3;
    int d2 = (q5 / 27) % 3;

    bool fast = (i + 4 <= n) && (r5 + 4 <= S5);

    if (fast) {
        const float4* in_re4  = reinterpret_cast<const float4*>(in_re);
        const float4* in_im4  = reinterpret_cast<const float4*>(in_im);
        float4*       out_re4 = reinterpret_cast<float4*>(out_re);

        float4 vr, vi;
        if (d2 != 1) {
            vr = __ldcs(in_re4 + q);         // LDG.E.128 streaming, coalesced
            vi = __ldcs(in_im4 + q);
        } else if (d5 == 2) {
            vr = make_float4(0.f, 0.f, 0.f, 0.f);
            vi = vr;
        } else {
            int s = (d5 == 0) ? (i + S5) : (i - S5);  // odd offset: scalar gather
            vr.x = __ldcs(in_re + s + 0);
            vr.y = __ldcs(in_re + s + 1);
            vr.z = __ldcs(in_re + s + 2);
            vr.w = __ldcs(in_re + s + 3);
            vi.x = __ldcs(in_im + s + 0);
            vi.y = __ldcs(in_im + s + 1);
            vi.z = __ldcs(in_im + s + 2);
            vi.w = __ldcs(in_im + s + 3);
        }
        __stcs(out_re4 + q, vr);             // STG.128 streaming (aligned)
        __stcs(out_im + i + 0, vi.x);        // STG.32 streaming x4 (coalesced)
        __stcs(out_im + i + 1, vi.y);
        __stcs(out_im + i + 2, vi.z);
        __stcs(out_im + i + 3, vi.w);
    } else {
        #pragma unroll
        for (int j = 0; j < 4; j++) {
            int idx = i + j;
            if (idx < n)
                scalar_one(in_re, in_im, out_re, out_im, idx);
        }
    }
}

extern "C" void kernel_launch(void* const* d_in, const int* in_sizes, int n_in,
                              void* d_out, int out_size)
{
    const float* in_re = (const float*)d_in[0];
    const float* in_im = (const float*)d_in[1];
    const int n = in_sizes[0];          // 3^16 = 43,046,721 (odd)

    float* out_re = (float*)d_out;
    float* out_im = (float*)d_out + n;  // 4B-aligned only

    const int nq = (n + 3) >> 2;
    const int threads = 512;
    const int blocks = (nq + threads - 1) / threads;
    sx_apply_final<<<blocks, threads>>>(in_re, in_im, out_re, out_im, n, nq);
}